// round 1
// baseline (speedup 1.0000x reference)
#include <cuda_runtime.h>
#include <cuda_bf16.h>
#include <cstdint>

// Problem constants (fixed for this dataset)
#define DD     1024      // bond dimension
#define NSYM   32        // alphabet
#define FF     1024      // chain length
#define HALF_F 512
#define GRP    64        // CTAs per direction
#define NTHR   256
#define COLS_PER_CTA 16  // DD / GRP (fwd: column slice, 32B/row sectors)
#define ROWS_PER_CTA 16  // DD / GRP (bwd: row slice, contiguous 2KB rows)

// Scratch (static __device__ globals are the allowed scratch mechanism)
__device__ __nv_bfloat16 g_core_bf[(size_t)NSYM * DD * DD];  // 64 MB, L2-resident
__device__ float g_v[2][DD];
__device__ float g_u[2][DD];

struct PadCnt { int v; int pad[31]; };   // 128B-isolated counters
__device__ PadCnt g_cnt_fwd, g_cnt_bwd, g_cnt_all;

// ---------------------------------------------------------------------------
// fp32 -> bf16 conversion of the 32 core matrices (runs every launch; 192 MB)
// ---------------------------------------------------------------------------
__global__ void convert_core_kernel(const float* __restrict__ core) {
    size_t i = ((size_t)blockIdx.x * NTHR + threadIdx.x) * 4;  // 4 elems/thread
    float4 f = *reinterpret_cast<const float4*>(core + i);
    __nv_bfloat162 lo = __floats2bfloat162_rn(f.x, f.y);
    __nv_bfloat162 hi = __floats2bfloat162_rn(f.z, f.w);
    uint2 o;
    o.x = *reinterpret_cast<unsigned*>(&lo);
    o.y = *reinterpret_cast<unsigned*>(&hi);
    *reinterpret_cast<uint2*>(g_core_bf + i) = o;
}

// ---------------------------------------------------------------------------
// per-launch init: reset barrier counters, load boundary vectors
// ---------------------------------------------------------------------------
__global__ void init_kernel(const float* __restrict__ left,
                            const float* __restrict__ right) {
    int t = threadIdx.x;
    g_v[0][t] = left[t];
    g_u[0][t] = right[t];
    if (t == 0) {
        g_cnt_fwd.v = 0;
        g_cnt_bwd.v = 0;
        g_cnt_all.v = 0;
    }
}

// ---------------------------------------------------------------------------
// Persistent chain kernel: blocks 0..63 forward (v <- v M), 64..127 backward
// (u <- M u). Monotonic counter barrier per group. Final dot by block 0.
// ---------------------------------------------------------------------------
__global__ __launch_bounds__(NTHR, 1)
void chain_kernel(const int* __restrict__ x, float* __restrict__ out) {
    __shared__ int   sx[HALF_F];
    __shared__ float red[8][16];

    const int tid = threadIdx.x;
    const bool is_fwd = (blockIdx.x < GRP);

    if (is_fwd) {
        // ============================ FORWARD ==============================
        const int b  = blockIdx.x;
        const int jb = b * COLS_PER_CTA;

        for (int i = tid; i < HALF_F; i += NTHR) sx[i] = x[i];
        __syncthreads();

        const int q = tid & 3;    // column quad within the 16-col slice
        const int g = tid >> 2;   // row group 0..63; rows g + 64*i

        for (int s = 0; s < HALF_F; ++s) {
            const int sym = sx[s];
            // ---- prefetch M[sym][g+64i][jb+4q .. +3] into registers (pre-barrier)
            const uint2* mp = reinterpret_cast<const uint2*>(
                g_core_bf + (size_t)sym * DD * DD + (size_t)g * DD + jb + 4 * q);
            uint2 pre[16];
#pragma unroll
            for (int i = 0; i < 16; ++i)
                pre[i] = __ldg(mp + (size_t)i * (64 * DD / 4));

            // ---- barrier: all fwd CTAs finished step s-1
            if (tid == 0) {
                volatile int* c = &g_cnt_fwd.v;
                while (*c < GRP * s) { }
                __threadfence();
            }
            __syncthreads();

            // ---- accumulate 4 output columns over 16 rows
            const float* vcur = g_v[s & 1];
            float a0 = 0.f, a1 = 0.f, a2 = 0.f, a3 = 0.f;
#pragma unroll
            for (int i = 0; i < 16; ++i) {
                float vv = __ldcg(&vcur[g + 64 * i]);     // L2-coherent read
                uint2 m = pre[i];
                a0 += vv * __uint_as_float(m.x << 16);
                a1 += vv * __uint_as_float(m.x & 0xffff0000u);
                a2 += vv * __uint_as_float(m.y << 16);
                a3 += vv * __uint_as_float(m.y & 0xffff0000u);
            }
            // reduce across row-groups within warp (lanes stride 4)
#pragma unroll
            for (int off = 16; off >= 4; off >>= 1) {
                a0 += __shfl_down_sync(0xffffffffu, a0, off);
                a1 += __shfl_down_sync(0xffffffffu, a1, off);
                a2 += __shfl_down_sync(0xffffffffu, a2, off);
                a3 += __shfl_down_sync(0xffffffffu, a3, off);
            }
            const int lane = tid & 31, w = tid >> 5;
            if (lane < 4) {
                red[w][lane * 4 + 0] = a0;
                red[w][lane * 4 + 1] = a1;
                red[w][lane * 4 + 2] = a2;
                red[w][lane * 4 + 3] = a3;
            }
            __syncthreads();

            float* vnext = g_v[(s + 1) & 1];
            if (tid < 16) {
                float sum = 0.f;
#pragma unroll
                for (int w2 = 0; w2 < 8; ++w2) sum += red[w2][tid];
                vnext[jb + tid] = sum;
                __threadfence();
            }
            __syncthreads();
            if (tid == 0) atomicAdd(&g_cnt_fwd.v, 1);
        }
    } else {
        // ============================ BACKWARD =============================
        const int c  = blockIdx.x - GRP;
        const int kb = c * ROWS_PER_CTA;

        for (int i = tid; i < HALF_F; i += NTHR) sx[i] = x[(FF - 1) - i];
        __syncthreads();

        const int r  = tid >> 4;   // row 0..15 within the slice
        const int ch = tid & 15;   // 64-col chunk

        for (int s = 0; s < HALF_F; ++s) {
            const int sym = sx[s];
            // ---- prefetch row M[sym][kb+r][ch*64 .. +63] (128B contiguous)
            const uint4* mp = reinterpret_cast<const uint4*>(
                g_core_bf + (size_t)sym * DD * DD + (size_t)(kb + r) * DD + ch * 64);
            uint4 pre[8];
#pragma unroll
            for (int i = 0; i < 8; ++i) pre[i] = __ldg(mp + i);

            if (tid == 0) {
                volatile int* cc = &g_cnt_bwd.v;
                while (*cc < GRP * s) { }
                __threadfence();
            }
            __syncthreads();

            const float* ucur = g_u[s & 1];
            float acc = 0.f;
#pragma unroll
            for (int i = 0; i < 8; ++i) {
                const int j0 = ch * 64 + i * 8;
                float4 u0 = __ldcg(reinterpret_cast<const float4*>(ucur + j0));
                float4 u1 = __ldcg(reinterpret_cast<const float4*>(ucur + j0 + 4));
                uint4 m = pre[i];
                acc += u0.x * __uint_as_float(m.x << 16);
                acc += u0.y * __uint_as_float(m.x & 0xffff0000u);
                acc += u0.z * __uint_as_float(m.y << 16);
                acc += u0.w * __uint_as_float(m.y & 0xffff0000u);
                acc += u1.x * __uint_as_float(m.z << 16);
                acc += u1.y * __uint_as_float(m.z & 0xffff0000u);
                acc += u1.z * __uint_as_float(m.w << 16);
                acc += u1.w * __uint_as_float(m.w & 0xffff0000u);
            }
            // reduce across 16 chunk-lanes (rows live at lanes 0 and 16)
#pragma unroll
            for (int off = 8; off >= 1; off >>= 1)
                acc += __shfl_down_sync(0xffffffffu, acc, off);

            float* unext = g_u[(s + 1) & 1];
            if ((tid & 15) == 0) {
                unext[kb + r] = acc;
                __threadfence();
            }
            __syncthreads();
            if (tid == 0) atomicAdd(&g_cnt_bwd.v, 1);
        }
    }

    // ======================== FINAL COMBINE ================================
    __threadfence();
    if (tid == 0) atomicAdd(&g_cnt_all.v, 1);

    if (blockIdx.x == 0) {
        if (tid == 0) {
            volatile int* c = &g_cnt_all.v;
            while (*c < 2 * GRP) { }
            __threadfence();
        }
        __syncthreads();

        float p = 0.f;
        for (int i = tid; i < DD; i += NTHR)
            p += __ldcg(&g_v[0][i]) * __ldcg(&g_u[0][i]);
#pragma unroll
        for (int off = 16; off >= 1; off >>= 1)
            p += __shfl_down_sync(0xffffffffu, p, off);

        __shared__ float fin[8];
        if ((tid & 31) == 0) fin[tid >> 5] = p;
        __syncthreads();
        if (tid == 0) {
            float t = 0.f;
#pragma unroll
            for (int w2 = 0; w2 < 8; ++w2) t += fin[w2];
            out[0] = t;
        }
    }
}

// ---------------------------------------------------------------------------
extern "C" void kernel_launch(void* const* d_in, const int* in_sizes, int n_in,
                              void* d_out, int out_size) {
    const int*   x     = (const int*)d_in[0];
    const float* core  = (const float*)d_in[1];   // (32, 1024, 1024) fp32
    const float* left  = (const float*)d_in[2];
    const float* right = (const float*)d_in[3];
    float* out = (float*)d_out;

    // 33,554,432 elements / 4 per thread / 256 threads = 32768 blocks
    convert_core_kernel<<<32768, NTHR>>>(core);
    init_kernel<<<1, DD>>>(left, right);
    chain_kernel<<<2 * GRP, NTHR>>>(x, out);
}

// round 3
// speedup vs baseline: 2.8293x; 2.8293x over previous
#include <cuda_runtime.h>
#include <cuda_bf16.h>
#include <cstdint>

#define DD     1024
#define NSYM   32
#define FF     1024
#define HALF_F 512
#define GRP    64        // CTAs per direction
#define NTHR   256
#define COLS_PER_CTA 16
#define ROWS_PER_CTA 16
#define SV_PAD(j) ((j) + ((j) >> 5))   // +1 float pad per 32 floats

__device__ __nv_bfloat16 g_core_bf[(size_t)NSYM * DD * DD];  // 64 MB, L2-resident
__device__ float g_v[2][DD];
__device__ float g_u[2][DD];

struct Flag { int v; int pad[31]; };     // 128B-isolated per-CTA flags
__device__ Flag g_flag_f[GRP];
__device__ Flag g_flag_b[GRP];

// ---------------------------------------------------------------------------
__device__ __forceinline__ int ld_relaxed(const int* p) {
    int v;
    asm volatile("ld.relaxed.gpu.b32 %0, [%1];" : "=r"(v) : "l"(p) : "memory");
    return v;
}
__device__ __forceinline__ void st_relaxed(int* p, int v) {
    asm volatile("st.relaxed.gpu.b32 [%0], %1;" :: "l"(p), "r"(v) : "memory");
}
__device__ __forceinline__ void fence_acqrel_gpu() {
    asm volatile("fence.acq_rel.gpu;" ::: "memory");
}

// ---------------------------------------------------------------------------
// fp32 -> bf16 conversion of the 32 core matrices (192 MB traffic, ~32us)
// ---------------------------------------------------------------------------
__global__ void convert_core_kernel(const float* __restrict__ core) {
    size_t i = ((size_t)blockIdx.x * NTHR + threadIdx.x) * 4;
    float4 f = *reinterpret_cast<const float4*>(core + i);
    __nv_bfloat162 lo = __floats2bfloat162_rn(f.x, f.y);
    __nv_bfloat162 hi = __floats2bfloat162_rn(f.z, f.w);
    uint2 o;
    o.x = *reinterpret_cast<unsigned*>(&lo);
    o.y = *reinterpret_cast<unsigned*>(&hi);
    *reinterpret_cast<uint2*>(g_core_bf + i) = o;
}

// ---------------------------------------------------------------------------
__global__ void init_kernel(const float* __restrict__ left,
                            const float* __restrict__ right) {
    int t = threadIdx.x;
    if (t < DD) {
        g_v[0][t] = left[t];
        g_u[0][t] = right[t];
    }
    if (t < GRP) {
        g_flag_f[t].v = 0;
        g_flag_b[t].v = 0;
    }
}

// ---------------------------------------------------------------------------
// Persistent chain: blocks 0..63 forward (v <- v M), 64..127 backward (u <- M u).
// Distributed-flag barrier: one flag/CTA, warp-parallel relaxed polling.
// ---------------------------------------------------------------------------
__global__ __launch_bounds__(NTHR, 1)
void chain_kernel(const int* __restrict__ x, float* __restrict__ out) {
    __shared__ int   sx[HALF_F];
    __shared__ float svec[DD + DD / 32];     // padded vector stage (full D)
    __shared__ float red[8][16];

    const int tid = threadIdx.x;
    const bool is_fwd = (blockIdx.x < GRP);

    if (is_fwd) {
        // ============================ FORWARD ==============================
        const int b  = blockIdx.x;
        const int jb = b * COLS_PER_CTA;

        for (int i = tid; i < HALF_F; i += NTHR) sx[i] = x[i];
        __syncthreads();

        const int q = tid & 3;    // column quad
        const int g = tid >> 2;   // row group 0..63; rows g + 64*i

        for (int s = 0; s < HALF_F; ++s) {
            const int sym = sx[s];
            // ---- prefetch (pre-barrier, pipelines under the sync path)
            const uint2* mp = reinterpret_cast<const uint2*>(
                g_core_bf + (size_t)sym * DD * DD + (size_t)g * DD + jb + 4 * q);
            uint2 pre[16];
#pragma unroll
            for (int i = 0; i < 16; ++i)
                pre[i] = __ldg(mp + (size_t)i * (64 * DD / 4));

            // ---- distributed barrier: wait until all fwd flags >= s
            if (tid < 32) {
                const int* fa = &g_flag_f[tid].v;
                const int* fb = &g_flag_f[tid + 32].v;
                while (!__all_sync(0xffffffffu,
                                   ld_relaxed(fa) >= s && ld_relaxed(fb) >= s)) { }
                fence_acqrel_gpu();
            }
            __syncthreads();

            // ---- stage FULL v (1024 floats = 256 thr x float4) into smem
            const float* vcur = g_v[s & 1];
            {
                int j0 = 4 * tid;
                float4 t4 = __ldcg(reinterpret_cast<const float4*>(vcur + j0));
                svec[SV_PAD(j0) + 0] = t4.x;   // j0 % 4 == 0 => same pad bucket
                svec[SV_PAD(j0) + 1] = t4.y;
                svec[SV_PAD(j0) + 2] = t4.z;
                svec[SV_PAD(j0) + 3] = t4.w;
            }
            __syncthreads();

            // ---- accumulate 4 output columns over 16 rows
            float a0 = 0.f, a1 = 0.f, a2 = 0.f, a3 = 0.f;
#pragma unroll
            for (int i = 0; i < 16; ++i) {
                float vv = svec[SV_PAD(g + 64 * i)];
                uint2 m = pre[i];
                a0 += vv * __uint_as_float(m.x << 16);
                a1 += vv * __uint_as_float(m.x & 0xffff0000u);
                a2 += vv * __uint_as_float(m.y << 16);
                a3 += vv * __uint_as_float(m.y & 0xffff0000u);
            }
#pragma unroll
            for (int off = 16; off >= 4; off >>= 1) {
                a0 += __shfl_down_sync(0xffffffffu, a0, off);
                a1 += __shfl_down_sync(0xffffffffu, a1, off);
                a2 += __shfl_down_sync(0xffffffffu, a2, off);
                a3 += __shfl_down_sync(0xffffffffu, a3, off);
            }
            const int lane = tid & 31, w = tid >> 5;
            if (lane < 4) {
                red[w][lane * 4 + 0] = a0;
                red[w][lane * 4 + 1] = a1;
                red[w][lane * 4 + 2] = a2;
                red[w][lane * 4 + 3] = a3;
            }
            __syncthreads();

            float* vnext = g_v[(s + 1) & 1];
            if (tid < 16) {
                float sum = 0.f;
#pragma unroll
                for (int w2 = 0; w2 < 8; ++w2) sum += red[w2][tid];
                __stcg(&vnext[jb + tid], sum);
            }
            __syncthreads();
            if (tid == 0) {
                fence_acqrel_gpu();                 // release our v writes
                st_relaxed(&g_flag_f[b].v, s + 1);  // announce step done
            }
        }
    } else {
        // ============================ BACKWARD =============================
        const int c  = blockIdx.x - GRP;
        const int kb = c * ROWS_PER_CTA;

        for (int i = tid; i < HALF_F; i += NTHR) sx[i] = x[(FF - 1) - i];
        __syncthreads();

        const int r  = tid >> 4;   // row within slice
        const int ch = tid & 15;   // 64-col chunk

        for (int s = 0; s < HALF_F; ++s) {
            const int sym = sx[s];
            const uint4* mp = reinterpret_cast<const uint4*>(
                g_core_bf + (size_t)sym * DD * DD + (size_t)(kb + r) * DD + ch * 64);
            uint4 pre[8];
#pragma unroll
            for (int i = 0; i < 8; ++i) pre[i] = __ldg(mp + i);

            if (tid < 32) {
                const int* fa = &g_flag_b[tid].v;
                const int* fb = &g_flag_b[tid + 32].v;
                while (!__all_sync(0xffffffffu,
                                   ld_relaxed(fa) >= s && ld_relaxed(fb) >= s)) { }
                fence_acqrel_gpu();
            }
            __syncthreads();

            // ---- stage FULL u into smem
            const float* ucur = g_u[s & 1];
            {
                int j0 = 4 * tid;
                float4 t4 = __ldcg(reinterpret_cast<const float4*>(ucur + j0));
                svec[SV_PAD(j0) + 0] = t4.x;
                svec[SV_PAD(j0) + 1] = t4.y;
                svec[SV_PAD(j0) + 2] = t4.z;
                svec[SV_PAD(j0) + 3] = t4.w;
            }
            __syncthreads();

            float acc = 0.f;
#pragma unroll
            for (int i = 0; i < 8; ++i) {
                const int j0 = ch * 64 + i * 8;
                uint4 m = pre[i];
                acc += svec[SV_PAD(j0 + 0)] * __uint_as_float(m.x << 16);
                acc += svec[SV_PAD(j0 + 1)] * __uint_as_float(m.x & 0xffff0000u);
                acc += svec[SV_PAD(j0 + 2)] * __uint_as_float(m.y << 16);
                acc += svec[SV_PAD(j0 + 3)] * __uint_as_float(m.y & 0xffff0000u);
                acc += svec[SV_PAD(j0 + 4)] * __uint_as_float(m.z << 16);
                acc += svec[SV_PAD(j0 + 5)] * __uint_as_float(m.z & 0xffff0000u);
                acc += svec[SV_PAD(j0 + 6)] * __uint_as_float(m.w << 16);
                acc += svec[SV_PAD(j0 + 7)] * __uint_as_float(m.w & 0xffff0000u);
            }
#pragma unroll
            for (int off = 8; off >= 1; off >>= 1)
                acc += __shfl_down_sync(0xffffffffu, acc, off);

            float* unext = g_u[(s + 1) & 1];
            if ((tid & 15) == 0)
                __stcg(&unext[kb + r], acc);
            __syncthreads();
            if (tid == 0) {
                fence_acqrel_gpu();
                st_relaxed(&g_flag_b[c].v, s + 1);
            }
        }
    }

    // ======================== FINAL COMBINE (block 0) ======================
    if (blockIdx.x == 0) {
        if (tid < 32) {
            const int* f0 = &g_flag_f[tid].v;
            const int* f1 = &g_flag_f[tid + 32].v;
            const int* f2 = &g_flag_b[tid].v;
            const int* f3 = &g_flag_b[tid + 32].v;
            while (!__all_sync(0xffffffffu,
                               ld_relaxed(f0) >= HALF_F && ld_relaxed(f1) >= HALF_F &&
                               ld_relaxed(f2) >= HALF_F && ld_relaxed(f3) >= HALF_F)) { }
            fence_acqrel_gpu();
        }
        __syncthreads();

        float p = 0.f;
        for (int i = tid; i < DD; i += NTHR)
            p += __ldcg(&g_v[0][i]) * __ldcg(&g_u[0][i]);
#pragma unroll
        for (int off = 16; off >= 1; off >>= 1)
            p += __shfl_down_sync(0xffffffffu, p, off);

        __shared__ float fin[8];
        if ((tid & 31) == 0) fin[tid >> 5] = p;
        __syncthreads();
        if (tid == 0) {
            float t = 0.f;
#pragma unroll
            for (int w2 = 0; w2 < 8; ++w2) t += fin[w2];
            out[0] = t;
        }
    }
}

// ---------------------------------------------------------------------------
extern "C" void kernel_launch(void* const* d_in, const int* in_sizes, int n_in,
                              void* d_out, int out_size) {
    const int*   x     = (const int*)d_in[0];
    const float* core  = (const float*)d_in[1];
    const float* left  = (const float*)d_in[2];
    const float* right = (const float*)d_in[3];
    float* out = (float*)d_out;

    convert_core_kernel<<<32768, NTHR>>>(core);
    init_kernel<<<1, 1024>>>(left, right);
    chain_kernel<<<2 * GRP, NTHR>>>(x, out);
}